// round 7
// baseline (speedup 1.0000x reference)
#include <cuda_runtime.h>

// DETRMatcher: reference's softmax/cdist/argmin are dead code w.r.t. outputs.
// Output = 8.1M float32:
//   [0, 1.62M)      : 0.0f           (two int32 zero index tensors)
//   [1.62M, 4.86M)  : outputs_coord  (bitwise copy)
//   [4.86M, 8.10M)  : target_boxes   (bitwise copy)
//
// R3/R5: three grid shapes all ~10.4-10.7us, meters ~32% -> not shape-bound.
// R6: branchless segment-specialized block ranges + streaming load hints
// (__ldcs) so the one-shot input reads don't evict the L2-resident output.

static constexpr int V_ZERO  = 405000;                 // float4 slots of zeros
static constexpr int V_COORD = 810000;                 // float4 slots per copy
static constexpr int TPB     = 256;

// Block budget: proportional to work, total ~1184 (one wave at occ 8).
static constexpr int B_ZERO  = 236;                    // ~1/5 of traffic (store-only)
static constexpr int B_COPY  = 474;                    // per copy segment
static constexpr int B_TOTAL = B_ZERO + 2 * B_COPY;    // 1184

__device__ __forceinline__ void copy_seg(const float4* __restrict__ src,
                                         float4* __restrict__ dst,
                                         int n, int bid, int nblocks)
{
    const int chunk = (n + nblocks - 1) / nblocks;
    const int start = bid * chunk;
    const int end   = min(start + chunk, n);

    int j = start + threadIdx.x;
    for (; j + 3 * TPB < end; j += 4 * TPB) {
        float4 v0 = __ldcs(src + j);
        float4 v1 = __ldcs(src + j +     TPB);
        float4 v2 = __ldcs(src + j + 2 * TPB);
        float4 v3 = __ldcs(src + j + 3 * TPB);
        __stcg(dst + j,           v0);
        __stcg(dst + j +     TPB, v1);
        __stcg(dst + j + 2 * TPB, v2);
        __stcg(dst + j + 3 * TPB, v3);
    }
    for (; j < end; j += TPB)
        __stcg(dst + j, __ldcs(src + j));
}

__global__ void __launch_bounds__(TPB)
detr_matcher_pack_f32(const float4* __restrict__ coord,
                      const float4* __restrict__ boxes,
                      float4* __restrict__ out)
{
    const int b = blockIdx.x;

    if (b < B_ZERO) {
        // Store-only zero fill of [0, V_ZERO)
        const int chunk = (V_ZERO + B_ZERO - 1) / B_ZERO;
        const int start = b * chunk;
        const int end   = min(start + chunk, V_ZERO);
        const float4 z = make_float4(0.f, 0.f, 0.f, 0.f);
        for (int j = start + threadIdx.x; j < end; j += TPB)
            __stcg(out + j, z);
    } else if (b < B_ZERO + B_COPY) {
        copy_seg(coord, out + V_ZERO, V_COORD, b - B_ZERO, B_COPY);
    } else {
        copy_seg(boxes, out + V_ZERO + V_COORD, V_COORD,
                 b - (B_ZERO + B_COPY), B_COPY);
    }
}

extern "C" void kernel_launch(void* const* d_in, const int* in_sizes, int n_in,
                              void* d_out, int out_size)
{
    // metadata order: outputs_class, outputs_coord, target_classes, target_boxes
    const float4* coord = (const float4*)d_in[1];
    const float4* boxes = (const float4*)d_in[3];
    float4* out = (float4*)d_out;

    detr_matcher_pack_f32<<<B_TOTAL, TPB>>>(coord, boxes, out);
}

// round 9
// speedup vs baseline: 1.0372x; 1.0372x over previous
#include <cuda_runtime.h>

// DETRMatcher: the reference's softmax/cdist/argmin are dead code w.r.t. the
// outputs (scatter of 0 into zeros = zeros). Output = 8.1M float32:
//   [0, 1.62M)      : 0.0f           (two int32 zero index tensors)
//   [1.62M, 4.86M)  : outputs_coord  (bitwise copy)
//   [4.86M, 8.10M)  : target_boxes   (bitwise copy)
//
// History: R2 flat-strided 10.18us (best ncu), R3 MLP4 10.37, R5 chunked 10.72,
// R6 cache-hints 11.46 — wall time bit-identical 10.719999us in ALL rounds ->
// harness replay-period floor. This round: lock in the fastest measured shape
// (flat strided, one float4 per thread) with copy branches resolved first.

static constexpr int V_ZERO  = 405000;                 // float4 slots of zeros
static constexpr int V_COORD = 810000;                 // float4 slots per copy
static constexpr int V_TOTAL = V_ZERO + 2 * V_COORD;   // 2,025,000
static constexpr int V_MID   = V_ZERO + V_COORD;       // 1,215,000

static constexpr int TPB = 512;

__global__ void __launch_bounds__(TPB)
detr_matcher_pack_f32(const float4* __restrict__ coord,
                      const float4* __restrict__ boxes,
                      float4* __restrict__ out)
{
    const int j = blockIdx.x * TPB + threadIdx.x;
    if (j >= V_TOTAL) return;

    float4 v;
    if (j >= V_MID) {                    // boxes copy (40% of elements)
        v = boxes[j - V_MID];
    } else if (j >= V_ZERO) {            // coord copy (40%)
        v = coord[j - V_ZERO];
    } else {                             // zero segment (20%)
        v = make_float4(0.f, 0.f, 0.f, 0.f);
    }
    out[j] = v;
}

extern "C" void kernel_launch(void* const* d_in, const int* in_sizes, int n_in,
                              void* d_out, int out_size)
{
    // metadata order: outputs_class, outputs_coord, target_classes, target_boxes
    const float4* coord = (const float4*)d_in[1];
    const float4* boxes = (const float4*)d_in[3];
    float4* out = (float4*)d_out;

    const int blocks = (V_TOTAL + TPB - 1) / TPB;   // 3956
    detr_matcher_pack_f32<<<blocks, TPB>>>(coord, boxes, out);
}